// round 1
// baseline (speedup 1.0000x reference)
#include <cuda_runtime.h>
#include <cuda_fp16.h>
#include <cstdint>

// MultiAttention fused kernel (round 0): mma.sync fp16 path.
// B=32768, T=8, DMODEL=256, H=4, DH=64. Rows = B*T = 262144.
// Per CTA: 128 rows (16 batch elements). Grid = 2048 CTAs, 256 threads.

#define NHEADS   4
#define SEQT     8
#define DM       256
#define DH       64
#define MTILE    128
#define AROW     264   // halves per row of X/O smem tiles (256 + 8 pad, 528B = 16B-aligned)
#define SROW     68    // halves per row of QKV staging (64 + 4 pad)
#define WS_OFF   33792                 // 128*264
#define STG_OFF  50688                 // WS_OFF + 64*264
#define STG_STRIDE 8704                // 128*68
#define OS_OFF   76800                 // STG_OFF + 3*8704
#define SMEM_HALVES 110592             // OS_OFF + 128*264
#define SMEM_BYTES  (SMEM_HALVES * 2)  // 221184 B

// fp16 weights, pre-transposed to [n][k] (B operand, n-major / "col" layout for mma)
__device__ __half g_Wqkv[768 * 256];   // rows 0-255: Q (h*64+e), 256-511: K, 512-767: V
__device__ __half g_Wfc[256 * 256];    // [n][k] = Wfc[k][n]

__global__ void prep_weights(const float* __restrict__ Wq, const float* __restrict__ Wk,
                             const float* __restrict__ Wv, const float* __restrict__ Wfc) {
    int idx = blockIdx.x * blockDim.x + threadIdx.x;  // 262144 total
    if (idx < 768 * 256) {
        int n = idx >> 8, d = idx & 255;
        int part = n >> 8;
        int hn = n & 255;
        int h = hn >> 6, e = hn & 63;
        const float* W = (part == 0) ? Wq : ((part == 1) ? Wk : Wv);
        g_Wqkv[idx] = __float2half(W[(h * DM + d) * DH + e]);
    } else {
        int j = idx - 768 * 256;
        int n = j >> 8, k = j & 255;
        g_Wfc[j] = __float2half(Wfc[k * 256 + n]);
    }
}

#define LDSM4(R0, R1, R2, R3, ADDR)                                            \
    asm volatile("ldmatrix.sync.aligned.m8n8.x4.shared.b16 {%0,%1,%2,%3}, [%4];\n" \
                 : "=r"(R0), "=r"(R1), "=r"(R2), "=r"(R3)                      \
                 : "r"(ADDR))

#define MMA16816(D, A, B)                                                      \
    asm volatile(                                                              \
        "mma.sync.aligned.m16n8k16.row.col.f32.f16.f16.f32 "                   \
        "{%0,%1,%2,%3}, {%4,%5,%6,%7}, {%8,%9}, {%0,%1,%2,%3};\n"              \
        : "+f"(D[0]), "+f"(D[1]), "+f"(D[2]), "+f"(D[3])                       \
        : "r"(A[0]), "r"(A[1]), "r"(A[2]), "r"(A[3]), "r"(B[0]), "r"(B[1]))

// One [128 x 64] chunk: C = A[128,256] @ Ws[64,256]^T, fp32 accum.
// Warp grid 4(m) x 2(n); warp tile 32x32.
__device__ __forceinline__ void gemm_chunk(const __half* A, const __half* Wsm,
                                           int wm, int wn, int lane,
                                           float acc[2][4][4]) {
    uint32_t Abase = (uint32_t)__cvta_generic_to_shared(A);
    uint32_t Wbase = (uint32_t)__cvta_generic_to_shared(Wsm);
    int r8 = lane & 7;
    int arow = (((lane >> 3) & 1) << 3) + r8;  // row-in-16 per ldmatrix tile order
    int ak   = (lane >> 4) << 3;               // k offset {0,8}
    int bn   = ((lane >> 4) << 3) + r8;        // n-in-16 per tile order
    int bk   = ((lane >> 3) & 1) << 3;         // k offset {0,8}

#pragma unroll
    for (int k0 = 0; k0 < DM; k0 += 16) {
        uint32_t a[2][4];
#pragma unroll
        for (int mi = 0; mi < 2; ++mi) {
            uint32_t addr = Abase + (uint32_t)(((wm + mi * 16 + arow) * AROW + k0 + ak) * 2);
            LDSM4(a[mi][0], a[mi][1], a[mi][2], a[mi][3], addr);
        }
        uint32_t b[4][2];
#pragma unroll
        for (int ni2 = 0; ni2 < 2; ++ni2) {
            uint32_t addr = Wbase + (uint32_t)(((wn + ni2 * 16 + bn) * AROW + k0 + bk) * 2);
            LDSM4(b[2 * ni2][0], b[2 * ni2][1], b[2 * ni2 + 1][0], b[2 * ni2 + 1][1], addr);
        }
#pragma unroll
        for (int mi = 0; mi < 2; ++mi)
#pragma unroll
            for (int ni = 0; ni < 4; ++ni) {
                MMA16816(acc[mi][ni], a[mi], b[ni]);
            }
    }
}

__global__ __launch_bounds__(256, 1)
void attn_main(const float* __restrict__ x, const float* __restrict__ bq,
               const float* __restrict__ bk, const float* __restrict__ bv,
               const float* __restrict__ bfc, float* __restrict__ out) {
    extern __shared__ __half sm[];
    __half* Xs  = sm;                 // [128][AROW] fp16 X tile
    __half* Ws  = sm + WS_OFF;        // [64][AROW]  fp16 weight chunk ([n][k])
    __half* Stg = sm + STG_OFF;       // 3 x [128][SROW]  q/k/v staging for current head
    __half* Os  = sm + OS_OFF;        // [128][AROW] fp16 head-concat output

    int tid = threadIdx.x, lane = tid & 31, wid = tid >> 5;
    int wm = (wid >> 1) * 32;         // warp m-origin: 0,32,64,96
    int wn = (wid & 1) * 32;          // warp n-origin: 0,32
    int row0 = blockIdx.x * MTILE;

    // ---- load X tile (fp32 global -> fp16 smem), coalesced float4 ----
#pragma unroll 4
    for (int i = tid; i < MTILE * 64; i += 256) {
        int r = i >> 6, c4 = i & 63;
        float4 v = reinterpret_cast<const float4*>(x)[(row0 + r) * 64 + c4];
        __half2* d = reinterpret_cast<__half2*>(Xs + r * AROW + c4 * 4);
        d[0] = __floats2half2_rn(v.x, v.y);
        d[1] = __floats2half2_rn(v.z, v.w);
    }
    __syncthreads();

    // ---- per-head: project q,k,v (N=64 chunks), then causal attention ----
    for (int h = 0; h < NHEADS; ++h) {
        for (int part = 0; part < 3; ++part) {
            int nbase = part * 256 + h * DH;
            // load W chunk [64][256] halves via uint4
            for (int i = tid; i < 64 * 32; i += 256) {
                int r = i >> 5, c8 = i & 31;
                reinterpret_cast<uint4*>(Ws + r * AROW)[c8] =
                    reinterpret_cast<const uint4*>(g_Wqkv + (nbase + r) * 256)[c8];
            }
            __syncthreads();

            float acc[2][4][4];
#pragma unroll
            for (int mi = 0; mi < 2; ++mi)
#pragma unroll
                for (int ni = 0; ni < 4; ++ni)
#pragma unroll
                    for (int c = 0; c < 4; ++c) acc[mi][ni][c] = 0.f;

            gemm_chunk(Xs, Ws, wm, wn, lane, acc);

            // epilogue: + bias, fp16, into staging
            const float* pb = (part == 0) ? bq : ((part == 1) ? bk : bv);
            __half* S = Stg + part * STG_STRIDE;
#pragma unroll
            for (int mi = 0; mi < 2; ++mi)
#pragma unroll
                for (int ni = 0; ni < 4; ++ni) {
                    int c = wn + ni * 8 + ((lane & 3) << 1);
                    float b0 = pb[h * DH + c], b1 = pb[h * DH + c + 1];
                    int r = wm + mi * 16 + (lane >> 2);
                    *reinterpret_cast<__half2*>(S + r * SROW + c) =
                        __floats2half2_rn(acc[mi][ni][0] + b0, acc[mi][ni][1] + b1);
                    *reinterpret_cast<__half2*>(S + (r + 8) * SROW + c) =
                        __floats2half2_rn(acc[mi][ni][2] + b0, acc[mi][ni][3] + b1);
                }
            __syncthreads();
        }

        // ---- causal attention for head h: one thread per row ----
        if (tid < MTILE) {
            int r = tid, base = r & ~7, t = r & 7;
            const __half2* qp = reinterpret_cast<const __half2*>(Stg + r * SROW);
            __half2 q2[32];
#pragma unroll
            for (int j = 0; j < 32; ++j) q2[j] = qp[j];

            float sc[SEQT];
#pragma unroll
            for (int s = 0; s < SEQT; ++s) {
                const __half2* kp =
                    reinterpret_cast<const __half2*>(Stg + STG_STRIDE + (base + s) * SROW);
                float a = 0.f;
#pragma unroll
                for (int j = 0; j < 32; ++j) {
                    __half2 p = __hmul2(q2[j], kp[j]);
                    a += __low2float(p) + __high2float(p);
                }
                sc[s] = a * 0.125f;  // 1/sqrt(64)
            }
            float m = sc[0];
#pragma unroll
            for (int s = 1; s < SEQT; ++s)
                if (s <= t && sc[s] > m) m = sc[s];
            float w[SEQT], sum = 0.f;
#pragma unroll
            for (int s = 0; s < SEQT; ++s) {
                w[s] = (s <= t) ? __expf(sc[s] - m) : 0.f;
                sum += w[s];
            }
            float inv = 1.f / sum;
            float o[DH];
#pragma unroll
            for (int j = 0; j < DH; ++j) o[j] = 0.f;
#pragma unroll
            for (int s = 0; s < SEQT; ++s) {
                float ws = w[s] * inv;  // 0 for s > t
                const __half2* vp =
                    reinterpret_cast<const __half2*>(Stg + 2 * STG_STRIDE + (base + s) * SROW);
#pragma unroll
                for (int j = 0; j < 32; ++j) {
                    __half2 v2 = vp[j];
                    o[2 * j]     += ws * __low2float(v2);
                    o[2 * j + 1] += ws * __high2float(v2);
                }
            }
            __half2* op = reinterpret_cast<__half2*>(Os + r * AROW + h * DH);
#pragma unroll
            for (int j = 0; j < 32; ++j) op[j] = __floats2half2_rn(o[2 * j], o[2 * j + 1]);
        }
        __syncthreads();
    }

    // ---- output projection: out = Os[128,256] @ Wfc + bfc ----
    for (int nc = 0; nc < 4; ++nc) {
        for (int i = tid; i < 64 * 32; i += 256) {
            int r = i >> 5, c8 = i & 31;
            reinterpret_cast<uint4*>(Ws + r * AROW)[c8] =
                reinterpret_cast<const uint4*>(g_Wfc + (nc * 64 + r) * 256)[c8];
        }
        __syncthreads();

        float acc[2][4][4];
#pragma unroll
        for (int mi = 0; mi < 2; ++mi)
#pragma unroll
            for (int ni = 0; ni < 4; ++ni)
#pragma unroll
                for (int c = 0; c < 4; ++c) acc[mi][ni][c] = 0.f;

        gemm_chunk(Os, Ws, wm, wn, lane, acc);

#pragma unroll
        for (int mi = 0; mi < 2; ++mi)
#pragma unroll
            for (int ni = 0; ni < 4; ++ni) {
                int c = nc * 64 + wn + ni * 8 + ((lane & 3) << 1);
                float b0 = bfc[c], b1 = bfc[c + 1];
                int r = wm + mi * 16 + (lane >> 2);
                float2 v0 = make_float2(acc[mi][ni][0] + b0, acc[mi][ni][1] + b1);
                float2 v1 = make_float2(acc[mi][ni][2] + b0, acc[mi][ni][3] + b1);
                *reinterpret_cast<float2*>(out + (row0 + r) * 256 + c) = v0;
                *reinterpret_cast<float2*>(out + (row0 + r + 8) * 256 + c) = v1;
            }
        __syncthreads();
    }
}

extern "C" void kernel_launch(void* const* d_in, const int* in_sizes, int n_in,
                              void* d_out, int out_size) {
    (void)in_sizes; (void)n_in; (void)out_size;
    const float* x   = (const float*)d_in[0];
    const float* Wq  = (const float*)d_in[1];
    const float* bq  = (const float*)d_in[2];
    const float* Wk  = (const float*)d_in[3];
    const float* bk  = (const float*)d_in[4];
    const float* Wv  = (const float*)d_in[5];
    const float* bv  = (const float*)d_in[6];
    const float* Wfc = (const float*)d_in[7];
    const float* bfc = (const float*)d_in[8];
    float* out = (float*)d_out;

    cudaFuncSetAttribute(attn_main, cudaFuncAttributeMaxDynamicSharedMemorySize, SMEM_BYTES);

    prep_weights<<<1024, 256>>>(Wq, Wk, Wv, Wfc);
    attn_main<<<2048, 256, SMEM_BYTES>>>(x, bq, bk, bv, bfc, out);
}

// round 2
// speedup vs baseline: 1.3213x; 1.3213x over previous
#include <cuda_runtime.h>
#include <cuda_fp16.h>
#include <cstdint>

// Round 1: M=64 tiles, 256 thr, 2 CTAs/SM. B operand pre-packed in mma
// fragment order in global (L1/L2-resident), loaded by LDG.64 — no weight
// smem, no weight barriers. Attention parallelized 4 threads/row.
// B=32768, T=8, DM=256, H=4, DH=64. Rows=262144. Grid=4096 x 256thr.

#define NHEADS 4
#define SEQT   8
#define DM     256
#define DH     64
#define MT     64
#define AROW   264                  // halves per row of Xs/Os (256+8 pad)
#define SROW   68                   // halves per row of qkv staging
#define STG_STRIDE (MT * SROW)      // 4352 halves
#define XS_HALVES  (MT * AROW)      // 16896
#define STG_OFF    XS_HALVES
#define OS_OFF     (XS_HALVES + 3 * STG_STRIDE)          // 29952
#define SMEM_HALVES (OS_OFF + MT * AROW)                 // 46848
#define SMEM_BYTES  (SMEM_HALVES * 2)                    // 93696

// 16 chunks (12 QKV: cid=h*3+part; 4 FC: cid=12+nc), each [N=64, K=256].
// Fragment order: [cid][kt(16)][nt(8)][lane(32)] -> uint2 (b0,b1 of m16n8k16).
__device__ uint2 g_frag[16 * 16 * 8 * 32];   // 512 KB

__global__ void prep_frags(const float* __restrict__ Wq, const float* __restrict__ Wk,
                           const float* __restrict__ Wv, const float* __restrict__ Wfc) {
    int g = blockIdx.x * 256 + threadIdx.x;          // 65536 threads
    int lane = g & 31, nt = (g >> 5) & 7, kt = (g >> 8) & 15, cid = g >> 12;
    int n  = nt * 8 + (lane >> 2);                   // local col 0..63
    int k0 = kt * 16 + ((lane & 3) << 1);            // k base for reg0
    float w0, w1, w2, w3;
    if (cid < 12) {
        int h = cid / 3, part = cid % 3;
        const float* W = (part == 0) ? Wq : ((part == 1) ? Wk : Wv);
        const float* p = W + h * DM * DH + n;        // W[h][k][n], stride DH
        w0 = p[k0 * DH]; w1 = p[(k0 + 1) * DH];
        w2 = p[(k0 + 8) * DH]; w3 = p[(k0 + 9) * DH];
    } else {
        int nc = cid - 12;
        const float* p = Wfc + nc * 64 + n;          // Wfc[k][n], stride 256
        w0 = p[k0 * 256]; w1 = p[(k0 + 1) * 256];
        w2 = p[(k0 + 8) * 256]; w3 = p[(k0 + 9) * 256];
    }
    __half2 lo = __floats2half2_rn(w0, w1), hi = __floats2half2_rn(w2, w3);
    uint2 v;
    v.x = *reinterpret_cast<uint32_t*>(&lo);
    v.y = *reinterpret_cast<uint32_t*>(&hi);
    g_frag[g] = v;
}

#define LDSM4(R0, R1, R2, R3, ADDR)                                                \
    asm volatile("ldmatrix.sync.aligned.m8n8.x4.shared.b16 {%0,%1,%2,%3}, [%4];\n" \
                 : "=r"(R0), "=r"(R1), "=r"(R2), "=r"(R3)                          \
                 : "r"(ADDR))

#define MMA16816(D, A0, A1, A2, A3, B0, B1)                                        \
    asm volatile(                                                                  \
        "mma.sync.aligned.m16n8k16.row.col.f32.f16.f16.f32 "                       \
        "{%0,%1,%2,%3}, {%4,%5,%6,%7}, {%8,%9}, {%0,%1,%2,%3};\n"                  \
        : "+f"(D[0]), "+f"(D[1]), "+f"(D[2]), "+f"(D[3])                           \
        : "r"(A0), "r"(A1), "r"(A2), "r"(A3), "r"(B0), "r"(B1))

// C[16x64] per warp: A[64,256] (smem, row pitch AROW) x chunk cid's B.
__device__ __forceinline__ void gemm_chunk(const __half* A, int cid,
                                           int wm, int wn, int lane,
                                           float acc[4][4]) {
    uint32_t Abase = (uint32_t)__cvta_generic_to_shared(A);
    int arow = (((lane >> 3) & 1) << 3) + (lane & 7);
    int ak   = (lane >> 4) << 3;
    uint32_t Aaddr0 = Abase + (uint32_t)(((wm + arow) * AROW + ak) * 2);
    const uint2* frag = g_frag + (cid * 128 + (wn >> 3)) * 32 + lane;
#pragma unroll
    for (int kt = 0; kt < 16; ++kt) {
        uint32_t a0, a1, a2, a3;
        LDSM4(a0, a1, a2, a3, Aaddr0 + (uint32_t)(kt * 32));
        uint2 b0 = frag[(kt * 8 + 0) * 32];
        uint2 b1 = frag[(kt * 8 + 1) * 32];
        uint2 b2 = frag[(kt * 8 + 2) * 32];
        uint2 b3 = frag[(kt * 8 + 3) * 32];
        MMA16816(acc[0], a0, a1, a2, a3, b0.x, b0.y);
        MMA16816(acc[1], a0, a1, a2, a3, b1.x, b1.y);
        MMA16816(acc[2], a0, a1, a2, a3, b2.x, b2.y);
        MMA16816(acc[3], a0, a1, a2, a3, b3.x, b3.y);
    }
}

__global__ __launch_bounds__(256, 2)
void attn_main(const float* __restrict__ x, const float* __restrict__ bq,
               const float* __restrict__ bk, const float* __restrict__ bv,
               const float* __restrict__ bfc, float* __restrict__ out) {
    extern __shared__ __half sm[];
    __half* Xs  = sm;             // [64][AROW]
    __half* Stg = sm + STG_OFF;   // 3 x [64][SROW]
    __half* Os  = sm + OS_OFF;    // [64][AROW]

    int tid = threadIdx.x, lane = tid & 31, wid = tid >> 5;
    int wm = (wid >> 1) * 16;     // 0,16,32,48
    int wn = (wid & 1) * 32;      // 0,32
    int row0 = blockIdx.x * MT;

    // ---- X tile: fp32 -> fp16 smem ----
#pragma unroll
    for (int i = tid; i < MT * 64; i += 256) {
        int r = i >> 6, c4 = i & 63;
        float4 v = reinterpret_cast<const float4*>(x)[(row0 + r) * 64 + c4];
        __half2* d = reinterpret_cast<__half2*>(Xs + r * AROW + c4 * 4);
        d[0] = __floats2half2_rn(v.x, v.y);
        d[1] = __floats2half2_rn(v.z, v.w);
    }
    __syncthreads();

    for (int h = 0; h < NHEADS; ++h) {
#pragma unroll
        for (int part = 0; part < 3; ++part) {
            float acc[4][4];
#pragma unroll
            for (int ni = 0; ni < 4; ++ni)
#pragma unroll
                for (int c = 0; c < 4; ++c) acc[ni][c] = 0.f;
            gemm_chunk(Xs, h * 3 + part, wm, wn, lane, acc);

            const float* pb = (part == 0) ? bq : ((part == 1) ? bk : bv);
            __half* S = Stg + part * STG_STRIDE;
            int r = wm + (lane >> 2);
            int cb = wn + ((lane & 3) << 1);
#pragma unroll
            for (int ni = 0; ni < 4; ++ni) {
                int c = cb + ni * 8;
                float b0 = pb[h * DH + c], b1 = pb[h * DH + c + 1];
                *reinterpret_cast<__half2*>(S + r * SROW + c) =
                    __floats2half2_rn(acc[ni][0] + b0, acc[ni][1] + b1);
                *reinterpret_cast<__half2*>(S + (r + 8) * SROW + c) =
                    __floats2half2_rn(acc[ni][2] + b0, acc[ni][3] + b1);
            }
        }
        __syncthreads();

        // ---- attention: 4 threads per row (row = tid>>2, qtr = tid&3) ----
        {
            int row = tid >> 2, qtr = tid & 3;
            int base = row & ~7, t = row & 7;
            const __half2* qp = reinterpret_cast<const __half2*>(Stg + row * SROW) + qtr * 8;
            __half2 q2[8];
#pragma unroll
            for (int j = 0; j < 8; ++j) q2[j] = qp[j];

            float sc[SEQT];
#pragma unroll
            for (int s = 0; s < SEQT; ++s) {
                const __half2* kp =
                    reinterpret_cast<const __half2*>(Stg + STG_STRIDE + (base + s) * SROW) + qtr * 8;
                float a = 0.f;
#pragma unroll
                for (int j = 0; j < 8; ++j) {
                    __half2 p = __hmul2(q2[j], kp[j]);
                    a += __low2float(p) + __high2float(p);
                }
                a += __shfl_xor_sync(0xffffffffu, a, 1);
                a += __shfl_xor_sync(0xffffffffu, a, 2);
                sc[s] = a * 0.125f;   // 1/sqrt(64)
            }
            float m = sc[0];
#pragma unroll
            for (int s = 1; s < SEQT; ++s)
                if (s <= t && sc[s] > m) m = sc[s];
            float w[SEQT], sum = 0.f;
#pragma unroll
            for (int s = 0; s < SEQT; ++s) {
                w[s] = (s <= t) ? __expf(sc[s] - m) : 0.f;
                sum += w[s];
            }
            float inv = 1.f / sum;
            float o[16];
#pragma unroll
            for (int j = 0; j < 16; ++j) o[j] = 0.f;
#pragma unroll
            for (int s = 0; s < SEQT; ++s) {
                float ws = w[s] * inv;
                const __half2* vp =
                    reinterpret_cast<const __half2*>(Stg + 2 * STG_STRIDE + (base + s) * SROW) + qtr * 8;
#pragma unroll
                for (int j = 0; j < 8; ++j) {
                    __half2 v2 = vp[j];
                    o[2 * j]     += ws * __low2float(v2);
                    o[2 * j + 1] += ws * __high2float(v2);
                }
            }
            __half2* op = reinterpret_cast<__half2*>(Os + row * AROW + h * DH + qtr * 16);
#pragma unroll
            for (int j = 0; j < 8; ++j) op[j] = __floats2half2_rn(o[2 * j], o[2 * j + 1]);
        }
        __syncthreads();
    }

    // ---- output projection: Os[64,256] @ Wfc + bfc -> out (fp32) ----
#pragma unroll
    for (int nc = 0; nc < 4; ++nc) {
        float acc[4][4];
#pragma unroll
        for (int ni = 0; ni < 4; ++ni)
#pragma unroll
            for (int c = 0; c < 4; ++c) acc[ni][c] = 0.f;
        gemm_chunk(Os, 12 + nc, wm, wn, lane, acc);

        int r = wm + (lane >> 2);
        int cb = nc * 64 + wn + ((lane & 3) << 1);
#pragma unroll
        for (int ni = 0; ni < 4; ++ni) {
            int c = cb + ni * 8;
            float b0 = bfc[c], b1 = bfc[c + 1];
            *reinterpret_cast<float2*>(out + (row0 + r) * 256 + c) =
                make_float2(acc[ni][0] + b0, acc[ni][1] + b1);
            *reinterpret_cast<float2*>(out + (row0 + r + 8) * 256 + c) =
                make_float2(acc[ni][2] + b0, acc[ni][3] + b1);
        }
    }
}

extern "C" void kernel_launch(void* const* d_in, const int* in_sizes, int n_in,
                              void* d_out, int out_size) {
    (void)in_sizes; (void)n_in; (void)out_size;
    const float* x   = (const float*)d_in[0];
    const float* Wq  = (const float*)d_in[1];
    const float* bq  = (const float*)d_in[2];
    const float* Wk  = (const float*)d_in[3];
    const float* bk  = (const float*)d_in[4];
    const float* Wv  = (const float*)d_in[5];
    const float* bv  = (const float*)d_in[6];
    const float* Wfc = (const float*)d_in[7];
    const float* bfc = (const float*)d_in[8];
    float* out = (float*)d_out;

    cudaFuncSetAttribute(attn_main, cudaFuncAttributeMaxDynamicSharedMemorySize, SMEM_BYTES);

    prep_frags<<<256, 256>>>(Wq, Wk, Wv, Wfc);
    attn_main<<<4096, 256, SMEM_BYTES>>>(x, bq, bk, bv, bfc, out);
}